// round 2
// baseline (speedup 1.0000x reference)
#include <cuda_runtime.h>
#include <math.h>

#define MROWS  4096   // B*S
#define DDIM   2048
#define NHEADS 16
#define HDIM   128
#define SEQ    2048
#define BATCH  2

// Scratch buffers (static device globals; no runtime allocation)
__device__ float g_Q[MROWS * DDIM];
__device__ float g_K[MROWS * DDIM];
__device__ float g_V[MROWS * DDIM];
__device__ float g_Att[MROWS * DDIM];

// ---------------------------------------------------------------------------
// GEMM (NT): Y[m][n] = sum_k X[m][k] * W[n][k] + bias[n]
// X: [Mdim][Kdim] row-major, W: [Ndim][Kdim] row-major (torch Linear weight)
// 128x128 block tile, BK=16, 256 threads, 8x8 per thread, reg prefetch.
// ---------------------------------------------------------------------------
__global__ __launch_bounds__(256)
void gemm_nt_bias_k(const float* __restrict__ X, const float* __restrict__ W,
                    const float* __restrict__ bias, float* __restrict__ Y,
                    int Mdim, int Ndim, int Kdim)
{
    __shared__ float As[16][132];   // [k][m]
    __shared__ float Bs[16][132];   // [k][n]

    const int tid = threadIdx.x;
    const int m0 = blockIdx.y * 128;
    const int n0 = blockIdx.x * 128;
    const int lr = tid >> 2;          // 0..63
    const int lc = (tid & 3) << 2;    // 0,4,8,12
    const float* Xp = X + (size_t)(m0 + lr) * Kdim + lc;
    const float* Wp = W + (size_t)(n0 + lr) * Kdim + lc;
    const size_t rowskip = (size_t)64 * Kdim;
    const int ty = tid >> 4;          // 0..15
    const int tx = tid & 15;          // 0..15

    float acc[8][8];
#pragma unroll
    for (int i = 0; i < 8; i++)
#pragma unroll
        for (int j = 0; j < 8; j++) acc[i][j] = 0.f;

    float4 xa = *(const float4*)(Xp);
    float4 xb = *(const float4*)(Xp + rowskip);
    float4 wa = *(const float4*)(Wp);
    float4 wb = *(const float4*)(Wp + rowskip);

    for (int k0 = 0; k0 < Kdim; k0 += 16) {
        As[lc+0][lr]    = xa.x; As[lc+1][lr]    = xa.y; As[lc+2][lr]    = xa.z; As[lc+3][lr]    = xa.w;
        As[lc+0][lr+64] = xb.x; As[lc+1][lr+64] = xb.y; As[lc+2][lr+64] = xb.z; As[lc+3][lr+64] = xb.w;
        Bs[lc+0][lr]    = wa.x; Bs[lc+1][lr]    = wa.y; Bs[lc+2][lr]    = wa.z; Bs[lc+3][lr]    = wa.w;
        Bs[lc+0][lr+64] = wb.x; Bs[lc+1][lr+64] = wb.y; Bs[lc+2][lr+64] = wb.z; Bs[lc+3][lr+64] = wb.w;
        __syncthreads();
        if (k0 + 16 < Kdim) {
            xa = *(const float4*)(Xp + k0 + 16);
            xb = *(const float4*)(Xp + k0 + 16 + rowskip);
            wa = *(const float4*)(Wp + k0 + 16);
            wb = *(const float4*)(Wp + k0 + 16 + rowskip);
        }
#pragma unroll
        for (int k = 0; k < 16; k++) {
            float a[8], b[8];
            *(float4*)(a)     = *(const float4*)&As[k][ty * 8];
            *(float4*)(a + 4) = *(const float4*)&As[k][ty * 8 + 4];
            *(float4*)(b)     = *(const float4*)&Bs[k][tx * 8];
            *(float4*)(b + 4) = *(const float4*)&Bs[k][tx * 8 + 4];
#pragma unroll
            for (int i = 0; i < 8; i++)
#pragma unroll
                for (int j = 0; j < 8; j++)
                    acc[i][j] = fmaf(a[i], b[j], acc[i][j]);
        }
        __syncthreads();
    }

    float bl[8];
#pragma unroll
    for (int j = 0; j < 8; j++) bl[j] = bias[n0 + tx * 8 + j];
#pragma unroll
    for (int i = 0; i < 8; i++) {
        float* yp = Y + (size_t)(m0 + ty * 8 + i) * Ndim + n0 + tx * 8;
        float4 o0 = make_float4(acc[i][0] + bl[0], acc[i][1] + bl[1],
                                acc[i][2] + bl[2], acc[i][3] + bl[3]);
        float4 o1 = make_float4(acc[i][4] + bl[4], acc[i][5] + bl[5],
                                acc[i][6] + bl[6], acc[i][7] + bl[7]);
        *(float4*)(yp)     = o0;
        *(float4*)(yp + 4) = o1;
    }
}

// ---------------------------------------------------------------------------
// Flash attention (fp32, online softmax).
// Grid: (SEQ/64, NHEADS, BATCH). Block: 256 threads.
// BM=64 query rows, BN=128 key rows per tile, Hd=128.
// Score/AV micro-tile: 8 rows (warp-uniform -> broadcast LDS) x 4 cols
// (cols = lane + {0,32,64,96} -> conflict-free LDS on K/V).
// ---------------------------------------------------------------------------
#define FA_BM 64
#define FA_BN 128
#define FA_QS 132   // row stride for sQ/sK/sV
#define FA_SS 132   // row stride for sS
#define FA_SMEM_FLOATS (FA_BM*FA_QS + 2*FA_BN*FA_QS + FA_BM*FA_SS + 3*FA_BM)
#define FA_SMEM_BYTES  (FA_SMEM_FLOATS * 4)

__global__ __launch_bounds__(256)
void flash_attn_k(const float* __restrict__ Q, const float* __restrict__ K,
                  const float* __restrict__ V, float* __restrict__ O)
{
    extern __shared__ float sm[];
    float* sQ  = sm;                      // [64][132]
    float* sK  = sQ + FA_BM * FA_QS;      // [128][132]
    float* sV  = sK + FA_BN * FA_QS;      // [128][132]
    float* sS  = sV + FA_BN * FA_QS;      // [64][132]
    float* sM  = sS + FA_BM * FA_SS;      // [64]
    float* sL  = sM + FA_BM;              // [64]
    float* sAl = sL + FA_BM;              // [64]

    const int tid = threadIdx.x;
    const int qt = blockIdx.x, h = blockIdx.y, b = blockIdx.z;
    const float scale = 0.08838834764831845f;  // 1/sqrt(128)

    const size_t headoff = (size_t)b * SEQ * DDIM + (size_t)h * HDIM;
    const float* Qg = Q + headoff + (size_t)qt * FA_BM * DDIM;

    // Load Q tile (pre-scaled)
    for (int i = tid; i < FA_BM * (HDIM / 4); i += 256) {
        int r = i >> 5, c4 = (i & 31) << 2;
        float4 v = *(const float4*)(Qg + (size_t)r * DDIM + c4);
        v.x *= scale; v.y *= scale; v.z *= scale; v.w *= scale;
        *(float4*)&sQ[r * FA_QS + c4] = v;
    }
    if (tid < FA_BM) { sM[tid] = -3.0e38f; sL[tid] = 0.f; }

    const int w  = tid >> 5;
    const int r0 = w << 3;        // 8 rows per warp (warp-uniform)
    const int nl = tid & 31;      // column lane

    float acc[8][4];
#pragma unroll
    for (int i = 0; i < 8; i++)
#pragma unroll
        for (int j = 0; j < 4; j++) acc[i][j] = 0.f;

    for (int jt = 0; jt < SEQ / FA_BN; jt++) {
        __syncthreads();   // prev AV done before overwriting sK/sV; first iter: Q load done
        const float* Kg = K + headoff + (size_t)jt * FA_BN * DDIM;
        const float* Vg = V + headoff + (size_t)jt * FA_BN * DDIM;
        for (int i = tid; i < FA_BN * (HDIM / 4); i += 256) {
            int r = i >> 5, c4 = (i & 31) << 2;
            *(float4*)&sK[r * FA_QS + c4] = *(const float4*)(Kg + (size_t)r * DDIM + c4);
            *(float4*)&sV[r * FA_QS + c4] = *(const float4*)(Vg + (size_t)r * DDIM + c4);
        }
        __syncthreads();

        // ---- scores: S = (Q*scale) . K^T, 8x4 per thread ----
        float sc[8][4];
#pragma unroll
        for (int i = 0; i < 8; i++)
#pragma unroll
            for (int j = 0; j < 4; j++) sc[i][j] = 0.f;

#pragma unroll 2
        for (int kk = 0; kk < HDIM; kk += 4) {
            float4 qa[8], kb[4];
#pragma unroll
            for (int i = 0; i < 8; i++)
                qa[i] = *(const float4*)&sQ[(r0 + i) * FA_QS + kk];
#pragma unroll
            for (int j = 0; j < 4; j++)
                kb[j] = *(const float4*)&sK[(nl + 32 * j) * FA_QS + kk];
#pragma unroll
            for (int i = 0; i < 8; i++)
#pragma unroll
                for (int j = 0; j < 4; j++)
                    sc[i][j] += qa[i].x * kb[j].x + qa[i].y * kb[j].y
                              + qa[i].z * kb[j].z + qa[i].w * kb[j].w;
        }
#pragma unroll
        for (int i = 0; i < 8; i++)
#pragma unroll
            for (int j = 0; j < 4; j++)
                sS[(r0 + i) * FA_SS + nl + 32 * j] = sc[i][j];
        __syncthreads();

        // ---- online softmax: 4 lanes per row, 32 cols each ----
        {
            const int r = tid >> 2, p4 = tid & 3;
            float* row = &sS[r * FA_SS + p4 * 32];
            float mloc = -3.0e38f;
#pragma unroll
            for (int c = 0; c < 32; c++) mloc = fmaxf(mloc, row[c]);
            mloc = fmaxf(mloc, __shfl_xor_sync(0xffffffffu, mloc, 1));
            mloc = fmaxf(mloc, __shfl_xor_sync(0xffffffffu, mloc, 2));
            const float mprev = sM[r];
            const float mnew  = fmaxf(mprev, mloc);
            const float alpha = __expf(mprev - mnew);
            float ls = 0.f;
#pragma unroll
            for (int c = 0; c < 32; c++) {
                float pv = __expf(row[c] - mnew);
                row[c] = pv;
                ls += pv;
            }
            ls += __shfl_xor_sync(0xffffffffu, ls, 1);
            ls += __shfl_xor_sync(0xffffffffu, ls, 2);
            if (p4 == 0) { sM[r] = mnew; sL[r] = fmaf(sL[r], alpha, ls); sAl[r] = alpha; }
        }
        __syncthreads();

        // ---- AV accumulate: acc = acc*alpha + P . V ----
        float al[8];
#pragma unroll
        for (int i = 0; i < 8; i++) al[i] = sAl[r0 + i];
#pragma unroll
        for (int i = 0; i < 8; i++)
#pragma unroll
            for (int j = 0; j < 4; j++) acc[i][j] *= al[i];

#pragma unroll 2
        for (int n = 0; n < FA_BN; n += 4) {
            float4 pr[8];
#pragma unroll
            for (int i = 0; i < 8; i++)
                pr[i] = *(const float4*)&sS[(r0 + i) * FA_SS + n];
#pragma unroll
            for (int nn = 0; nn < 4; nn++) {
                float vj[4];
#pragma unroll
                for (int j = 0; j < 4; j++)
                    vj[j] = sV[(n + nn) * FA_QS + nl + 32 * j];
#pragma unroll
                for (int i = 0; i < 8; i++) {
                    float p = (nn == 0) ? pr[i].x : (nn == 1) ? pr[i].y
                            : (nn == 2) ? pr[i].z : pr[i].w;
#pragma unroll
                    for (int j = 0; j < 4; j++)
                        acc[i][j] = fmaf(p, vj[j], acc[i][j]);
                }
            }
        }
    }
    __syncthreads();

    // epilogue: divide by l, store
    float* Og = O + headoff + (size_t)qt * FA_BM * DDIM;
#pragma unroll
    for (int i = 0; i < 8; i++) {
        const float linv = 1.f / sL[r0 + i];
#pragma unroll
        for (int j = 0; j < 4; j++)
            Og[(size_t)(r0 + i) * DDIM + nl + 32 * j] = acc[i][j] * linv;
    }
}

// ---------------------------------------------------------------------------
extern "C" void kernel_launch(void* const* d_in, const int* in_sizes, int n_in,
                              void* d_out, int out_size)
{
    (void)in_sizes; (void)n_in; (void)out_size;
    const float* query  = (const float*)d_in[0];
    const float* key_in = (const float*)d_in[1];
    const float* value  = (const float*)d_in[2];
    const float* Wq = (const float*)d_in[3];
    const float* bq = (const float*)d_in[4];
    const float* Wk = (const float*)d_in[5];
    const float* bk = (const float*)d_in[6];
    const float* Wv = (const float*)d_in[7];
    const float* bv = (const float*)d_in[8];
    const float* Wo = (const float*)d_in[9];
    const float* bo = (const float*)d_in[10];
    float* out = (float*)d_out;

    float *pQ, *pK, *pV, *pA;
    cudaGetSymbolAddress((void**)&pQ, g_Q);
    cudaGetSymbolAddress((void**)&pK, g_K);
    cudaGetSymbolAddress((void**)&pV, g_V);
    cudaGetSymbolAddress((void**)&pA, g_Att);

    dim3 gg(DDIM / 128, MROWS / 128);
    gemm_nt_bias_k<<<gg, 256>>>(query,  Wq, bq, pQ, MROWS, DDIM, DDIM);
    gemm_nt_bias_k<<<gg, 256>>>(key_in, Wk, bk, pK, MROWS, DDIM, DDIM);
    gemm_nt_bias_k<<<gg, 256>>>(value,  Wv, bv, pV, MROWS, DDIM, DDIM);

    cudaFuncSetAttribute(flash_attn_k,
                         cudaFuncAttributeMaxDynamicSharedMemorySize, FA_SMEM_BYTES);
    flash_attn_k<<<dim3(SEQ / FA_BM, NHEADS, BATCH), 256, FA_SMEM_BYTES>>>(pQ, pK, pV, pA);

    gemm_nt_bias_k<<<gg, 256>>>(pA, Wo, bo, out, MROWS, DDIM, DDIM);
}

// round 3
// speedup vs baseline: 1.0101x; 1.0101x over previous
#include <cuda_runtime.h>
#include <math.h>

#define MROWS  4096   // B*S
#define DDIM   2048
#define NHEADS 16
#define HDIM   128
#define SEQ    2048
#define BATCH  2

typedef unsigned long long ull;

// Scratch buffers (static device globals; no runtime allocation)
__device__ float g_Q[MROWS * DDIM];
__device__ float g_K[MROWS * DDIM];
__device__ float g_V[MROWS * DDIM];
__device__ float g_Att[MROWS * DDIM];

// ---- packed f32x2 helpers (Blackwell) --------------------------------------
__device__ __forceinline__ ull pack2(float lo, float hi) {
    ull r;
    asm("mov.b64 %0, {%1, %2};" : "=l"(r) : "f"(lo), "f"(hi));
    return r;
}
__device__ __forceinline__ void ffma2(ull& d, ull a, ull b) {
    asm("fma.rn.f32x2 %0, %1, %2, %0;" : "+l"(d) : "l"(a), "l"(b));
}
__device__ __forceinline__ ull mul2(ull a, ull b) {
    ull r;
    asm("mul.rn.f32x2 %0, %1, %2;" : "=l"(r) : "l"(a), "l"(b));
    return r;
}
__device__ __forceinline__ float2 unpack2(ull v) {
    float2 f;
    asm("mov.b64 {%0, %1}, %2;" : "=f"(f.x), "=f"(f.y) : "l"(v));
    return f;
}

// ---------------------------------------------------------------------------
// GEMM (NT): Y[m][n] = sum_k X[m][k] * W[n][k] + bias[n]
// 128x128 block tile, BK=16, 256 threads, 8x8 per thread (f32x2 packed over j).
// ---------------------------------------------------------------------------
__global__ __launch_bounds__(256, 2)
void gemm_nt_bias_k(const float* __restrict__ X, const float* __restrict__ W,
                    const float* __restrict__ bias, float* __restrict__ Y,
                    int Mdim, int Ndim, int Kdim)
{
    __shared__ float As[16][132];   // [k][m]
    __shared__ float Bs[16][132];   // [k][n]

    const int tid = threadIdx.x;
    const int m0 = blockIdx.y * 128;
    const int n0 = blockIdx.x * 128;
    const int lr = tid >> 2;          // 0..63
    const int lc = (tid & 3) << 2;    // 0,4,8,12
    const float* Xp = X + (size_t)(m0 + lr) * Kdim + lc;
    const float* Wp = W + (size_t)(n0 + lr) * Kdim + lc;
    const size_t rowskip = (size_t)64 * Kdim;
    const int ty = tid >> 4;          // 0..15
    const int tx = tid & 15;          // 0..15

    ull acc2[8][4];                   // (j even, j odd) pairs
#pragma unroll
    for (int i = 0; i < 8; i++)
#pragma unroll
        for (int j = 0; j < 4; j++) acc2[i][j] = 0ULL;

    float4 xa = *(const float4*)(Xp);
    float4 xb = *(const float4*)(Xp + rowskip);
    float4 wa = *(const float4*)(Wp);
    float4 wb = *(const float4*)(Wp + rowskip);

    for (int k0 = 0; k0 < Kdim; k0 += 16) {
        As[lc+0][lr]    = xa.x; As[lc+1][lr]    = xa.y; As[lc+2][lr]    = xa.z; As[lc+3][lr]    = xa.w;
        As[lc+0][lr+64] = xb.x; As[lc+1][lr+64] = xb.y; As[lc+2][lr+64] = xb.z; As[lc+3][lr+64] = xb.w;
        Bs[lc+0][lr]    = wa.x; Bs[lc+1][lr]    = wa.y; Bs[lc+2][lr]    = wa.z; Bs[lc+3][lr]    = wa.w;
        Bs[lc+0][lr+64] = wb.x; Bs[lc+1][lr+64] = wb.y; Bs[lc+2][lr+64] = wb.z; Bs[lc+3][lr+64] = wb.w;
        __syncthreads();
        if (k0 + 16 < Kdim) {
            xa = *(const float4*)(Xp + k0 + 16);
            xb = *(const float4*)(Xp + k0 + 16 + rowskip);
            wa = *(const float4*)(Wp + k0 + 16);
            wb = *(const float4*)(Wp + k0 + 16 + rowskip);
        }
#pragma unroll
        for (int k = 0; k < 16; k++) {
            float a[8];
            *(float4*)(a)     = *(const float4*)&As[k][ty * 8];
            *(float4*)(a + 4) = *(const float4*)&As[k][ty * 8 + 4];
            ulonglong2 bp0 = *(const ulonglong2*)&Bs[k][tx * 8];       // (b0,b1),(b2,b3)
            ulonglong2 bp1 = *(const ulonglong2*)&Bs[k][tx * 8 + 4];   // (b4,b5),(b6,b7)
#pragma unroll
            for (int i = 0; i < 8; i++) {
                ull ai = pack2(a[i], a[i]);
                ffma2(acc2[i][0], ai, bp0.x);
                ffma2(acc2[i][1], ai, bp0.y);
                ffma2(acc2[i][2], ai, bp1.x);
                ffma2(acc2[i][3], ai, bp1.y);
            }
        }
        __syncthreads();
    }

    float bl[8];
#pragma unroll
    for (int j = 0; j < 8; j++) bl[j] = bias[n0 + tx * 8 + j];
#pragma unroll
    for (int i = 0; i < 8; i++) {
        float* yp = Y + (size_t)(m0 + ty * 8 + i) * Ndim + n0 + tx * 8;
        float2 p0 = unpack2(acc2[i][0]);
        float2 p1 = unpack2(acc2[i][1]);
        float2 p2 = unpack2(acc2[i][2]);
        float2 p3 = unpack2(acc2[i][3]);
        float4 o0 = make_float4(p0.x + bl[0], p0.y + bl[1], p1.x + bl[2], p1.y + bl[3]);
        float4 o1 = make_float4(p2.x + bl[4], p2.y + bl[5], p3.x + bl[6], p3.y + bl[7]);
        *(float4*)(yp)     = o0;
        *(float4*)(yp + 4) = o1;
    }
}

// ---------------------------------------------------------------------------
// Flash attention (fp32, online softmax) with f32x2 inner loops.
// Grid: (SEQ/64, NHEADS, BATCH). Block: 256 threads.
// BM=64 query rows, BN=128 key rows per tile, Hd=128.
// ---------------------------------------------------------------------------
#define FA_BM 64
#define FA_BN 128
#define FA_QS 132   // row stride for sQ/sK/sV
#define FA_SS 132   // row stride for sS
#define FA_SMEM_FLOATS (FA_BM*FA_QS + 2*FA_BN*FA_QS + FA_BM*FA_SS + 3*FA_BM)
#define FA_SMEM_BYTES  (FA_SMEM_FLOATS * 4)

__global__ __launch_bounds__(256)
void flash_attn_k(const float* __restrict__ Q, const float* __restrict__ K,
                  const float* __restrict__ V, float* __restrict__ O)
{
    extern __shared__ float sm[];
    float* sQ  = sm;                      // [64][132]
    float* sK  = sQ + FA_BM * FA_QS;      // [128][132]
    float* sV  = sK + FA_BN * FA_QS;      // [128][132]
    float* sS  = sV + FA_BN * FA_QS;      // [64][132]
    float* sM  = sS + FA_BM * FA_SS;      // [64]
    float* sL  = sM + FA_BM;              // [64]
    float* sAl = sL + FA_BM;              // [64]

    const int tid = threadIdx.x;
    const int qt = blockIdx.x, h = blockIdx.y, b = blockIdx.z;
    const float scale = 0.08838834764831845f;  // 1/sqrt(128)

    const size_t headoff = (size_t)b * SEQ * DDIM + (size_t)h * HDIM;
    const float* Qg = Q + headoff + (size_t)qt * FA_BM * DDIM;

    // Load Q tile (pre-scaled)
    for (int i = tid; i < FA_BM * (HDIM / 4); i += 256) {
        int r = i >> 5, c4 = (i & 31) << 2;
        float4 v = *(const float4*)(Qg + (size_t)r * DDIM + c4);
        v.x *= scale; v.y *= scale; v.z *= scale; v.w *= scale;
        *(float4*)&sQ[r * FA_QS + c4] = v;
    }
    if (tid < FA_BM) { sM[tid] = -3.0e38f; sL[tid] = 0.f; }

    const int w  = tid >> 5;
    const int r0 = w << 3;        // 8 rows per warp (warp-uniform)
    const int nl = tid & 31;      // column lane

    ull acc2[8][4];               // packed over n-parity
#pragma unroll
    for (int i = 0; i < 8; i++)
#pragma unroll
        for (int j = 0; j < 4; j++) acc2[i][j] = 0ULL;

    for (int jt = 0; jt < SEQ / FA_BN; jt++) {
        __syncthreads();   // prev AV done before overwriting sK/sV; first iter: Q load done
        const float* Kg = K + headoff + (size_t)jt * FA_BN * DDIM;
        const float* Vg = V + headoff + (size_t)jt * FA_BN * DDIM;
        for (int i = tid; i < FA_BN * (HDIM / 4); i += 256) {
            int r = i >> 5, c4 = (i & 31) << 2;
            *(float4*)&sK[r * FA_QS + c4] = *(const float4*)(Kg + (size_t)r * DDIM + c4);
            *(float4*)&sV[r * FA_QS + c4] = *(const float4*)(Vg + (size_t)r * DDIM + c4);
        }
        __syncthreads();

        // ---- scores: S = (Q*scale) . K^T, 8x4 per thread, packed over k-parity
        ull sc2[8][4];
#pragma unroll
        for (int i = 0; i < 8; i++)
#pragma unroll
            for (int j = 0; j < 4; j++) sc2[i][j] = 0ULL;

#pragma unroll 2
        for (int kk = 0; kk < HDIM; kk += 4) {
            ulonglong2 q2[8], k2[4];
#pragma unroll
            for (int i = 0; i < 8; i++)
                q2[i] = *(const ulonglong2*)&sQ[(r0 + i) * FA_QS + kk];
#pragma unroll
            for (int j = 0; j < 4; j++)
                k2[j] = *(const ulonglong2*)&sK[(nl + 32 * j) * FA_QS + kk];
#pragma unroll
            for (int i = 0; i < 8; i++)
#pragma unroll
                for (int j = 0; j < 4; j++) {
                    ffma2(sc2[i][j], q2[i].x, k2[j].x);
                    ffma2(sc2[i][j], q2[i].y, k2[j].y);
                }
        }
#pragma unroll
        for (int i = 0; i < 8; i++)
#pragma unroll
            for (int j = 0; j < 4; j++) {
                float2 p = unpack2(sc2[i][j]);
                sS[(r0 + i) * FA_SS + nl + 32 * j] = p.x + p.y;
            }
        __syncthreads();

        // ---- online softmax: 4 lanes per row, 32 cols each ----
        {
            const int r = tid >> 2, p4 = tid & 3;
            float* row = &sS[r * FA_SS + p4 * 32];
            float mloc = -3.0e38f;
#pragma unroll
            for (int c = 0; c < 32; c++) mloc = fmaxf(mloc, row[c]);
            mloc = fmaxf(mloc, __shfl_xor_sync(0xffffffffu, mloc, 1));
            mloc = fmaxf(mloc, __shfl_xor_sync(0xffffffffu, mloc, 2));
            const float mprev = sM[r];
            const float mnew  = fmaxf(mprev, mloc);
            const float alpha = __expf(mprev - mnew);
            float ls = 0.f;
#pragma unroll
            for (int c = 0; c < 32; c++) {
                float pv = __expf(row[c] - mnew);
                row[c] = pv;
                ls += pv;
            }
            ls += __shfl_xor_sync(0xffffffffu, ls, 1);
            ls += __shfl_xor_sync(0xffffffffu, ls, 2);
            if (p4 == 0) { sM[r] = mnew; sL[r] = fmaf(sL[r], alpha, ls); sAl[r] = alpha; }
        }
        __syncthreads();

        // ---- AV accumulate: acc = acc*alpha + P . V  (packed over n-parity)
#pragma unroll
        for (int i = 0; i < 8; i++) {
            ull al2 = pack2(sAl[r0 + i], sAl[r0 + i]);
#pragma unroll
            for (int j = 0; j < 4; j++) acc2[i][j] = mul2(acc2[i][j], al2);
        }

#pragma unroll 2
        for (int n = 0; n < FA_BN; n += 2) {
            ull p2[8];
#pragma unroll
            for (int i = 0; i < 8; i++)
                p2[i] = *(const ull*)&sS[(r0 + i) * FA_SS + n];   // (P[i][n],P[i][n+1])
            ull v2[4];
#pragma unroll
            for (int j = 0; j < 4; j++)
                v2[j] = pack2(sV[n * FA_QS + nl + 32 * j],
                              sV[(n + 1) * FA_QS + nl + 32 * j]);
#pragma unroll
            for (int i = 0; i < 8; i++)
#pragma unroll
                for (int j = 0; j < 4; j++)
                    ffma2(acc2[i][j], p2[i], v2[j]);
        }
    }
    __syncthreads();

    // epilogue: horizontal add, divide by l, store
    float* Og = O + headoff + (size_t)qt * FA_BM * DDIM;
#pragma unroll
    for (int i = 0; i < 8; i++) {
        const float linv = 1.f / sL[r0 + i];
#pragma unroll
        for (int j = 0; j < 4; j++) {
            float2 p = unpack2(acc2[i][j]);
            Og[(size_t)(r0 + i) * DDIM + nl + 32 * j] = (p.x + p.y) * linv;
        }
    }
}

// ---------------------------------------------------------------------------
extern "C" void kernel_launch(void* const* d_in, const int* in_sizes, int n_in,
                              void* d_out, int out_size)
{
    (void)in_sizes; (void)n_in; (void)out_size;
    const float* query  = (const float*)d_in[0];
    const float* key_in = (const float*)d_in[1];
    const float* value  = (const float*)d_in[2];
    const float* Wq = (const float*)d_in[3];
    const float* bq = (const float*)d_in[4];
    const float* Wk = (const float*)d_in[5];
    const float* bk = (const float*)d_in[6];
    const float* Wv = (const float*)d_in[7];
    const float* bv = (const float*)d_in[8];
    const float* Wo = (const float*)d_in[9];
    const float* bo = (const float*)d_in[10];
    float* out = (float*)d_out;

    float *pQ, *pK, *pV, *pA;
    cudaGetSymbolAddress((void**)&pQ, g_Q);
    cudaGetSymbolAddress((void**)&pK, g_K);
    cudaGetSymbolAddress((void**)&pV, g_V);
    cudaGetSymbolAddress((void**)&pA, g_Att);

    dim3 gg(DDIM / 128, MROWS / 128);
    gemm_nt_bias_k<<<gg, 256>>>(query,  Wq, bq, pQ, MROWS, DDIM, DDIM);
    gemm_nt_bias_k<<<gg, 256>>>(key_in, Wk, bk, pK, MROWS, DDIM, DDIM);
    gemm_nt_bias_k<<<gg, 256>>>(value,  Wv, bv, pV, MROWS, DDIM, DDIM);

    cudaFuncSetAttribute(flash_attn_k,
                         cudaFuncAttributeMaxDynamicSharedMemorySize, FA_SMEM_BYTES);
    flash_attn_k<<<dim3(SEQ / FA_BM, NHEADS, BATCH), 256, FA_SMEM_BYTES>>>(pQ, pK, pV, pA);

    gemm_nt_bias_k<<<gg, 256>>>(pA, Wo, bo, out, MROWS, DDIM, DDIM);
}

// round 5
// speedup vs baseline: 1.5074x; 1.4923x over previous
#include <cuda_runtime.h>
#include <cuda_bf16.h>
#include <math.h>
#include <stdint.h>

#define MROWS  4096   // B*S
#define DDIM   2048
#define NHEADS 16
#define HDIM   128
#define SEQ    2048
#define BATCH  2

typedef unsigned long long ull;

// Scratch buffers (static device globals; no runtime allocation)
__device__ float g_Q[MROWS * DDIM];
__device__ float g_K[MROWS * DDIM];
__device__ float g_V[MROWS * DDIM];
__device__ float g_Att[MROWS * DDIM];

// ---- packed f32x2 helpers (flash kernel) -----------------------------------
__device__ __forceinline__ ull pack2(float lo, float hi) {
    ull r;
    asm("mov.b64 %0, {%1, %2};" : "=l"(r) : "f"(lo), "f"(hi));
    return r;
}
__device__ __forceinline__ void ffma2(ull& d, ull a, ull b) {
    asm("fma.rn.f32x2 %0, %1, %2, %0;" : "+l"(d) : "l"(a), "l"(b));
}
__device__ __forceinline__ ull mul2(ull a, ull b) {
    ull r;
    asm("mul.rn.f32x2 %0, %1, %2;" : "=l"(r) : "l"(a), "l"(b));
    return r;
}
__device__ __forceinline__ float2 unpack2(ull v) {
    float2 f;
    asm("mov.b64 {%0, %1}, %2;" : "=f"(f.x), "=f"(f.y) : "l"(v));
    return f;
}

// ---- mma.sync helpers -------------------------------------------------------
__device__ __forceinline__ uint32_t smem_u32(const void* p) {
    uint32_t a;
    asm("{ .reg .u64 t; cvta.to.shared.u64 t, %1; cvt.u32.u64 %0, t; }"
        : "=r"(a) : "l"(p));
    return a;
}
__device__ __forceinline__ uint32_t sw128(uint32_t off) {
    return off ^ ((off >> 3) & 0x70);
}
__device__ __forceinline__ void ldmx4(uint32_t* r, uint32_t addr) {
    asm volatile("ldmatrix.sync.aligned.m8n8.x4.shared.b16 {%0,%1,%2,%3}, [%4];"
                 : "=r"(r[0]), "=r"(r[1]), "=r"(r[2]), "=r"(r[3]) : "r"(addr));
}
__device__ __forceinline__ void mma_bf16(float* c, const uint32_t* a,
                                         uint32_t b0, uint32_t b1) {
    asm volatile(
        "mma.sync.aligned.m16n8k16.row.col.f32.bf16.bf16.f32 "
        "{%0,%1,%2,%3}, {%4,%5,%6,%7}, {%8,%9}, {%0,%1,%2,%3};"
        : "+f"(c[0]), "+f"(c[1]), "+f"(c[2]), "+f"(c[3])
        : "r"(a[0]), "r"(a[1]), "r"(a[2]), "r"(a[3]), "r"(b0), "r"(b1));
}

// ---------------------------------------------------------------------------
// Tensor-core GEMM (NT, split-bf16 3xMMA via mma.sync):
//   Y[m][n] = sum_k X[m][k] * W[n][k] + bias[n]
// CTA tile 128x128, BK=64, 512 threads (4x4 warps, 32x32 warp tile).
// fp32->bf16 hi/lo conversion fused into the smem load path.
// ---------------------------------------------------------------------------
#define GT_TILE_B (128 * 64 * 2)                 // 16384 B per bf16 tile
#define GT_SMEM   (4 * GT_TILE_B + 1024)         // 4 tiles + align slack

__global__ __launch_bounds__(512)
void gemm_mma_k(const float* __restrict__ X, const float* __restrict__ W,
                const float* __restrict__ bias, float* __restrict__ Y)
{
    extern __shared__ char dsm[];
    char* smc = (char*)(((uintptr_t)dsm + 1023) & ~(uintptr_t)1023);
    char* smAhi = smc;
    char* smAlo = smc + GT_TILE_B;
    char* smBhi = smc + 2 * GT_TILE_B;
    char* smBlo = smc + 3 * GT_TILE_B;
    const uint32_t sAhi = smem_u32(smAhi);
    const uint32_t sAlo = sAhi + GT_TILE_B;
    const uint32_t sBhi = sAhi + 2 * GT_TILE_B;
    const uint32_t sBlo = sAhi + 3 * GT_TILE_B;

    const int tid  = threadIdx.x;
    const int wid  = tid >> 5;
    const int lane = tid & 31;
    const int wm = wid >> 2;        // 0..3
    const int wn = wid & 3;         // 0..3
    const int m0 = blockIdx.y * 128;
    const int n0 = blockIdx.x * 128;

    float acc[2][4][4];             // [m16 tile][n8 tile][frag]
#pragma unroll
    for (int i = 0; i < 2; i++)
#pragma unroll
        for (int j = 0; j < 4; j++)
#pragma unroll
            for (int q = 0; q < 4; q++) acc[i][j][q] = 0.f;

    // ldmatrix lane addressing (within warp tile), constant over chunks
    const int a_row = wm * 32 + (lane & 15);               // A rows for x4
    const int a_cb  = (lane >> 4) * 16;                    // +0/+16 bytes
    const int b_row = wn * 32 + (lane & 7) + ((lane >> 4) << 3);
    const int b_cb  = ((lane >> 3) & 1) * 16;

    for (int chunk = 0; chunk < DDIM / 64; chunk++) {
        const int k0 = chunk * 64;
        __syncthreads();   // prior mma reads done before smem overwrite

        // load + convert: each operand 128 rows x 16 chunks of 16B fp32
#pragma unroll
        for (int t = 0; t < 4; t++) {
            const int c   = tid + t * 512;
            const int row = c >> 4;
            const int ch  = c & 15;
            const uint32_t soff = sw128((uint32_t)(row * 128 + ch * 8));
            {
                float4 v = *(const float4*)(X + (size_t)(m0 + row) * DDIM + k0 + ch * 4);
                __nv_bfloat162 h01 = __floats2bfloat162_rn(v.x, v.y);
                __nv_bfloat162 h23 = __floats2bfloat162_rn(v.z, v.w);
                float2 g01 = __bfloat1622float2(h01);
                float2 g23 = __bfloat1622float2(h23);
                __nv_bfloat162 l01 = __floats2bfloat162_rn(v.x - g01.x, v.y - g01.y);
                __nv_bfloat162 l23 = __floats2bfloat162_rn(v.z - g23.x, v.w - g23.y);
                *(uint2*)(smAhi + soff) = make_uint2(*(uint32_t*)&h01, *(uint32_t*)&h23);
                *(uint2*)(smAlo + soff) = make_uint2(*(uint32_t*)&l01, *(uint32_t*)&l23);
            }
            {
                float4 v = *(const float4*)(W + (size_t)(n0 + row) * DDIM + k0 + ch * 4);
                __nv_bfloat162 h01 = __floats2bfloat162_rn(v.x, v.y);
                __nv_bfloat162 h23 = __floats2bfloat162_rn(v.z, v.w);
                float2 g01 = __bfloat1622float2(h01);
                float2 g23 = __bfloat1622float2(h23);
                __nv_bfloat162 l01 = __floats2bfloat162_rn(v.x - g01.x, v.y - g01.y);
                __nv_bfloat162 l23 = __floats2bfloat162_rn(v.z - g23.x, v.w - g23.y);
                *(uint2*)(smBhi + soff) = make_uint2(*(uint32_t*)&h01, *(uint32_t*)&h23);
                *(uint2*)(smBlo + soff) = make_uint2(*(uint32_t*)&l01, *(uint32_t*)&l23);
            }
        }
        __syncthreads();

#pragma unroll
        for (int ks = 0; ks < 4; ks++) {
            const uint32_t kb = ks * 32;   // 16 bf16 = 32 bytes per k16 step
            uint32_t ah[2][4], al[2][4], bh[2][4], bl[2][4];
#pragma unroll
            for (int mt = 0; mt < 2; mt++) {
                const uint32_t off =
                    sw128((uint32_t)((a_row + mt * 16) * 128) + kb + a_cb);
                ldmx4(ah[mt], sAhi + off);
                ldmx4(al[mt], sAlo + off);
            }
#pragma unroll
            for (int nt = 0; nt < 2; nt++) {
                const uint32_t off =
                    sw128((uint32_t)((b_row + nt * 16) * 128) + kb + b_cb);
                ldmx4(bh[nt], sBhi + off);
                ldmx4(bl[nt], sBlo + off);
            }
#pragma unroll
            for (int mt = 0; mt < 2; mt++)
#pragma unroll
                for (int nt = 0; nt < 2; nt++)
#pragma unroll
                    for (int h = 0; h < 2; h++) {
                        float* c = acc[mt][nt * 2 + h];
                        mma_bf16(c, ah[mt], bh[nt][2 * h], bh[nt][2 * h + 1]);
                        mma_bf16(c, ah[mt], bl[nt][2 * h], bl[nt][2 * h + 1]);
                        mma_bf16(c, al[mt], bh[nt][2 * h], bh[nt][2 * h + 1]);
                    }
        }
    }

    // epilogue: add bias, store fp32
    const int g  = lane >> 2;
    const int tg = lane & 3;
#pragma unroll
    for (int mt = 0; mt < 2; mt++) {
        const int row = m0 + wm * 32 + mt * 16 + g;
#pragma unroll
        for (int nt8 = 0; nt8 < 4; nt8++) {
            const int col = n0 + wn * 32 + nt8 * 8 + tg * 2;
            const float b0 = bias[col], b1 = bias[col + 1];
            float* y0 = Y + (size_t)row * DDIM + col;
            float* y1 = Y + (size_t)(row + 8) * DDIM + col;
            y0[0] = acc[mt][nt8][0] + b0;
            y0[1] = acc[mt][nt8][1] + b1;
            y1[0] = acc[mt][nt8][2] + b0;
            y1[1] = acc[mt][nt8][3] + b1;
        }
    }
}

// ---------------------------------------------------------------------------
// Flash attention (fp32, online softmax) with f32x2 inner loops. (unchanged)
// ---------------------------------------------------------------------------
#define FA_BM 64
#define FA_BN 128
#define FA_QS 132
#define FA_SS 132
#define FA_SMEM_FLOATS (FA_BM*FA_QS + 2*FA_BN*FA_QS + FA_BM*FA_SS + 3*FA_BM)
#define FA_SMEM_BYTES  (FA_SMEM_FLOATS * 4)

__global__ __launch_bounds__(256)
void flash_attn_k(const float* __restrict__ Q, const float* __restrict__ K,
                  const float* __restrict__ V, float* __restrict__ O)
{
    extern __shared__ float sm[];
    float* sQ  = sm;
    float* sK  = sQ + FA_BM * FA_QS;
    float* sV  = sK + FA_BN * FA_QS;
    float* sS  = sV + FA_BN * FA_QS;
    float* sM  = sS + FA_BM * FA_SS;
    float* sL  = sM + FA_BM;
    float* sAl = sL + FA_BM;

    const int tid = threadIdx.x;
    const int qt = blockIdx.x, h = blockIdx.y, b = blockIdx.z;
    const float scale = 0.08838834764831845f;

    const size_t headoff = (size_t)b * SEQ * DDIM + (size_t)h * HDIM;
    const float* Qg = Q + headoff + (size_t)qt * FA_BM * DDIM;

    for (int i = tid; i < FA_BM * (HDIM / 4); i += 256) {
        int r = i >> 5, c4 = (i & 31) << 2;
        float4 v = *(const float4*)(Qg + (size_t)r * DDIM + c4);
        v.x *= scale; v.y *= scale; v.z *= scale; v.w *= scale;
        *(float4*)&sQ[r * FA_QS + c4] = v;
    }
    if (tid < FA_BM) { sM[tid] = -3.0e38f; sL[tid] = 0.f; }

    const int w  = tid >> 5;
    const int r0 = w << 3;
    const int nl = tid & 31;

    ull acc2[8][4];
#pragma unroll
    for (int i = 0; i < 8; i++)
#pragma unroll
        for (int j = 0; j < 4; j++) acc2[i][j] = 0ULL;

    for (int jt = 0; jt < SEQ / FA_BN; jt++) {
        __syncthreads();
        const float* Kg = K + headoff + (size_t)jt * FA_BN * DDIM;
        const float* Vg = V + headoff + (size_t)jt * FA_BN * DDIM;
        for (int i = tid; i < FA_BN * (HDIM / 4); i += 256) {
            int r = i >> 5, c4 = (i & 31) << 2;
            *(float4*)&sK[r * FA_QS + c4] = *(const float4*)(Kg + (size_t)r * DDIM + c4);
            *(float4*)&sV[r * FA_QS + c4] = *(const float4*)(Vg + (size_t)r * DDIM + c4);
        }
        __syncthreads();

        ull sc2[8][4];
#pragma unroll
        for (int i = 0; i < 8; i++)
#pragma unroll
            for (int j = 0; j < 4; j++) sc2[i][j] = 0ULL;

#pragma unroll 2
        for (int kk = 0; kk < HDIM; kk += 4) {
            ulonglong2 q2[8], k2[4];
#pragma unroll
            for (int i = 0; i < 8; i++)
                q2[i] = *(const ulonglong2*)&sQ[(r0 + i) * FA_QS + kk];
#pragma unroll
            for (int j = 0; j < 4; j++)
                k2[j] = *(const ulonglong2*)&sK[(nl + 32 * j) * FA_QS + kk];
#pragma unroll
            for (int i = 0; i < 8; i++)
#pragma unroll
                for (int j = 0; j < 4; j++) {
                    ffma2(sc2[i][j], q2[i].x, k2[j].x);
                    ffma2(sc2[i][j], q2[i].y, k2[j].y);
                }
        }
#pragma unroll
        for (int i = 0; i < 8; i++)
#pragma unroll
            for (int j = 0; j < 4; j++) {
                float2 p = unpack2(sc2[i][j]);
                sS[(r0 + i) * FA_SS + nl + 32 * j] = p.x + p.y;
            }
        __syncthreads();

        {
            const int r = tid >> 2, p4 = tid & 3;
            float* row = &sS[r * FA_SS + p4 * 32];
            float mloc = -3.0e38f;
#pragma unroll
            for (int c = 0; c < 32; c++) mloc = fmaxf(mloc, row[c]);
            mloc = fmaxf(mloc, __shfl_xor_sync(0xffffffffu, mloc, 1));
            mloc = fmaxf(mloc, __shfl_xor_sync(0xffffffffu, mloc, 2));
            const float mprev = sM[r];
            const float mnew  = fmaxf(mprev, mloc);
            const float alpha = __expf(mprev - mnew);
            float ls = 0.f;
#pragma unroll
            for (int c = 0; c < 32; c++) {
                float pv = __expf(row[c] - mnew);
                row[c] = pv;
                ls += pv;
            }
            ls += __shfl_xor_sync(0xffffffffu, ls, 1);
            ls += __shfl_xor_sync(0xffffffffu, ls, 2);
            if (p4 == 0) { sM[r] = mnew; sL[r] = fmaf(sL[r], alpha, ls); sAl[r] = alpha; }
        }
        __syncthreads();

#pragma unroll
        for (int i = 0; i < 8; i++) {
            ull al2 = pack2(sAl[r0 + i], sAl[r0 + i]);
#pragma unroll
            for (int j = 0; j < 4; j++) acc2[i][j] = mul2(acc2[i][j], al2);
        }

#pragma unroll 2
        for (int n = 0; n < FA_BN; n += 2) {
            ull p2[8];
#pragma unroll
            for (int i = 0; i < 8; i++)
                p2[i] = *(const ull*)&sS[(r0 + i) * FA_SS + n];
            ull v2[4];
#pragma unroll
            for (int j = 0; j < 4; j++)
                v2[j] = pack2(sV[n * FA_QS + nl + 32 * j],
                              sV[(n + 1) * FA_QS + nl + 32 * j]);
#pragma unroll
            for (int i = 0; i < 8; i++)
#pragma unroll
                for (int j = 0; j < 4; j++)
                    ffma2(acc2[i][j], p2[i], v2[j]);
        }
    }
    __syncthreads();

    float* Og = O + headoff + (size_t)qt * FA_BM * DDIM;
#pragma unroll
    for (int i = 0; i < 8; i++) {
        const float linv = 1.f / sL[r0 + i];
#pragma unroll
        for (int j = 0; j < 4; j++) {
            float2 p = unpack2(acc2[i][j]);
            Og[(size_t)(r0 + i) * DDIM + nl + 32 * j] = (p.x + p.y) * linv;
        }
    }
}

// ---------------------------------------------------------------------------
extern "C" void kernel_launch(void* const* d_in, const int* in_sizes, int n_in,
                              void* d_out, int out_size)
{
    (void)in_sizes; (void)n_in; (void)out_size;
    const float* query  = (const float*)d_in[0];
    const float* key_in = (const float*)d_in[1];
    const float* value  = (const float*)d_in[2];
    const float* Wq = (const float*)d_in[3];
    const float* bq = (const float*)d_in[4];
    const float* Wk = (const float*)d_in[5];
    const float* bk = (const float*)d_in[6];
    const float* Wv = (const float*)d_in[7];
    const float* bv = (const float*)d_in[8];
    const float* Wo = (const float*)d_in[9];
    const float* bo = (const float*)d_in[10];
    float* out = (float*)d_out;

    float *pQ, *pK, *pV, *pA;
    cudaGetSymbolAddress((void**)&pQ, g_Q);
    cudaGetSymbolAddress((void**)&pK, g_K);
    cudaGetSymbolAddress((void**)&pV, g_V);
    cudaGetSymbolAddress((void**)&pA, g_Att);

    cudaFuncSetAttribute(gemm_mma_k,
                         cudaFuncAttributeMaxDynamicSharedMemorySize, GT_SMEM);
    cudaFuncSetAttribute(flash_attn_k,
                         cudaFuncAttributeMaxDynamicSharedMemorySize, FA_SMEM_BYTES);

    dim3 gg(DDIM / 128, MROWS / 128);
    gemm_mma_k<<<gg, 512, GT_SMEM>>>(query,  Wq, bq, pQ);
    gemm_mma_k<<<gg, 512, GT_SMEM>>>(key_in, Wk, bk, pK);
    gemm_mma_k<<<gg, 512, GT_SMEM>>>(value,  Wv, bv, pV);

    flash_attn_k<<<dim3(SEQ / FA_BM, NHEADS, BATCH), 256, FA_SMEM_BYTES>>>(pQ, pK, pV, pA);

    gemm_mma_k<<<gg, 512, GT_SMEM>>>(pA, Wo, bo, out);
}

// round 6
// speedup vs baseline: 2.4618x; 1.6331x over previous
#include <cuda_runtime.h>
#include <cuda_fp16.h>
#include <math.h>
#include <stdint.h>

#define MROWS  4096   // B*S
#define DDIM   2048
#define NHEADS 16
#define HDIM   128
#define SEQ    2048
#define BATCH  2

// Scratch (static device globals; no runtime allocation)
__device__ __half g_Qhi[MROWS * DDIM];
__device__ __half g_Qlo[MROWS * DDIM];
__device__ __half g_Khi[MROWS * DDIM];
__device__ __half g_Klo[MROWS * DDIM];
__device__ __half g_Vhi[MROWS * DDIM];
__device__ __half g_Vlo[MROWS * DDIM];
__device__ float  g_Att[MROWS * DDIM];

// ---- common helpers ----------------------------------------------------------
__device__ __forceinline__ uint32_t smem_u32(const void* p) {
    uint32_t a;
    asm("{ .reg .u64 t; cvta.to.shared.u64 t, %1; cvt.u32.u64 %0, t; }"
        : "=r"(a) : "l"(p));
    return a;
}
__device__ __forceinline__ uint32_t sw128(uint32_t off) {
    return off ^ ((off >> 3) & 0x70);
}
__device__ __forceinline__ void ldmx4(uint32_t* r, uint32_t addr) {
    asm volatile("ldmatrix.sync.aligned.m8n8.x4.shared.b16 {%0,%1,%2,%3}, [%4];"
                 : "=r"(r[0]), "=r"(r[1]), "=r"(r[2]), "=r"(r[3]) : "r"(addr));
}
__device__ __forceinline__ void ldmx4t(uint32_t* r, uint32_t addr) {
    asm volatile("ldmatrix.sync.aligned.m8n8.x4.trans.shared.b16 {%0,%1,%2,%3}, [%4];"
                 : "=r"(r[0]), "=r"(r[1]), "=r"(r[2]), "=r"(r[3]) : "r"(addr));
}
__device__ __forceinline__ void mma_f16(float* c, const uint32_t* a,
                                        uint32_t b0, uint32_t b1) {
    asm volatile(
        "mma.sync.aligned.m16n8k16.row.col.f32.f16.f16.f32 "
        "{%0,%1,%2,%3}, {%4,%5,%6,%7}, {%8,%9}, {%0,%1,%2,%3};"
        : "+f"(c[0]), "+f"(c[1]), "+f"(c[2]), "+f"(c[3])
        : "r"(a[0]), "r"(a[1]), "r"(a[2]), "r"(a[3]), "r"(b0), "r"(b1));
}
// exp2 on packed pair: lo = 2^d0, hi = 2^d1 (f16x2) — a-fragment-ready
__device__ __forceinline__ uint32_t exp2x2(float d0, float d1) {
    uint32_t p;
    asm("{ .reg .b32 t;\n\t"
        "cvt.rn.f16x2.f32 t, %1, %2;\n\t"   // hi = %1(d1), lo = %2(d0)
        "ex2.approx.f16x2 %0, t; }"
        : "=r"(p) : "f"(d1), "f"(d0));
    return p;
}
__device__ __forceinline__ float ex2f(float x) {
    float r;
    asm("ex2.approx.ftz.f32 %0, %1;" : "=f"(r) : "f"(x));
    return r;
}

// ---------------------------------------------------------------------------
// Tensor-core GEMM (NT, split-f16 3xMMA): Y = X @ W^T + bias
// CTA 128x128, BK=64, 512 threads. Optionally emits f16 hi/lo split output.
// ---------------------------------------------------------------------------
#define GT_TILE_B (128 * 64 * 2)
#define GT_SMEM   (4 * GT_TILE_B + 1024)

__global__ __launch_bounds__(512)
void gemm_mma_k(const float* __restrict__ X, const float* __restrict__ W,
                const float* __restrict__ bias, float* __restrict__ Y,
                __half* __restrict__ Yhi, __half* __restrict__ Ylo)
{
    extern __shared__ char dsm[];
    char* smc = (char*)(((uintptr_t)dsm + 1023) & ~(uintptr_t)1023);
    char* smAhi = smc;
    char* smAlo = smc + GT_TILE_B;
    char* smBhi = smc + 2 * GT_TILE_B;
    char* smBlo = smc + 3 * GT_TILE_B;
    const uint32_t sAhi = smem_u32(smAhi);
    const uint32_t sAlo = sAhi + GT_TILE_B;
    const uint32_t sBhi = sAhi + 2 * GT_TILE_B;
    const uint32_t sBlo = sAhi + 3 * GT_TILE_B;

    const int tid  = threadIdx.x;
    const int wid  = tid >> 5;
    const int lane = tid & 31;
    const int wm = wid >> 2;
    const int wn = wid & 3;
    const int m0 = blockIdx.y * 128;
    const int n0 = blockIdx.x * 128;

    float acc[2][4][4];
#pragma unroll
    for (int i = 0; i < 2; i++)
#pragma unroll
        for (int j = 0; j < 4; j++)
#pragma unroll
            for (int q = 0; q < 4; q++) acc[i][j][q] = 0.f;

    const int a_row = wm * 32 + (lane & 15);
    const int a_cb  = (lane >> 4) * 16;
    const int b_row = wn * 32 + (lane & 7) + ((lane >> 4) << 3);
    const int b_cb  = ((lane >> 3) & 1) * 16;

    for (int chunk = 0; chunk < DDIM / 64; chunk++) {
        const int k0 = chunk * 64;
        __syncthreads();
#pragma unroll
        for (int t = 0; t < 4; t++) {
            const int c   = tid + t * 512;
            const int row = c >> 4;
            const int ch  = c & 15;
            const uint32_t soff = sw128((uint32_t)(row * 128 + ch * 8));
            {
                float4 v = *(const float4*)(X + (size_t)(m0 + row) * DDIM + k0 + ch * 4);
                __half2 h01 = __floats2half2_rn(v.x, v.y);
                __half2 h23 = __floats2half2_rn(v.z, v.w);
                float2 g01 = __half22float2(h01);
                float2 g23 = __half22float2(h23);
                __half2 l01 = __floats2half2_rn(v.x - g01.x, v.y - g01.y);
                __half2 l23 = __floats2half2_rn(v.z - g23.x, v.w - g23.y);
                *(uint2*)(smAhi + soff) = make_uint2(*(uint32_t*)&h01, *(uint32_t*)&h23);
                *(uint2*)(smAlo + soff) = make_uint2(*(uint32_t*)&l01, *(uint32_t*)&l23);
            }
            {
                float4 v = *(const float4*)(W + (size_t)(n0 + row) * DDIM + k0 + ch * 4);
                __half2 h01 = __floats2half2_rn(v.x, v.y);
                __half2 h23 = __floats2half2_rn(v.z, v.w);
                float2 g01 = __half22float2(h01);
                float2 g23 = __half22float2(h23);
                __half2 l01 = __floats2half2_rn(v.x - g01.x, v.y - g01.y);
                __half2 l23 = __floats2half2_rn(v.z - g23.x, v.w - g23.y);
                *(uint2*)(smBhi + soff) = make_uint2(*(uint32_t*)&h01, *(uint32_t*)&h23);
                *(uint2*)(smBlo + soff) = make_uint2(*(uint32_t*)&l01, *(uint32_t*)&l23);
            }
        }
        __syncthreads();

#pragma unroll
        for (int ks = 0; ks < 4; ks++) {
            const uint32_t kb = ks * 32;
            uint32_t ah[2][4], al[2][4], bh[2][4], bl[2][4];
#pragma unroll
            for (int mt = 0; mt < 2; mt++) {
                const uint32_t off =
                    sw128((uint32_t)((a_row + mt * 16) * 128) + kb + a_cb);
                ldmx4(ah[mt], sAhi + off);
                ldmx4(al[mt], sAlo + off);
            }
#pragma unroll
            for (int nt = 0; nt < 2; nt++) {
                const uint32_t off =
                    sw128((uint32_t)((b_row + nt * 16) * 128) + kb + b_cb);
                ldmx4(bh[nt], sBhi + off);
                ldmx4(bl[nt], sBlo + off);
            }
#pragma unroll
            for (int mt = 0; mt < 2; mt++)
#pragma unroll
                for (int nt = 0; nt < 2; nt++)
#pragma unroll
                    for (int h = 0; h < 2; h++) {
                        float* c = acc[mt][nt * 2 + h];
                        mma_f16(c, ah[mt], bh[nt][2 * h], bh[nt][2 * h + 1]);
                        mma_f16(c, ah[mt], bl[nt][2 * h], bl[nt][2 * h + 1]);
                        mma_f16(c, al[mt], bh[nt][2 * h], bh[nt][2 * h + 1]);
                    }
        }
    }

    const int g  = lane >> 2;
    const int tg = lane & 3;
#pragma unroll
    for (int mt = 0; mt < 2; mt++) {
        const int row = m0 + wm * 32 + mt * 16 + g;
#pragma unroll
        for (int nt8 = 0; nt8 < 4; nt8++) {
            const int col = n0 + wn * 32 + nt8 * 8 + tg * 2;
            const float b0 = bias[col], b1 = bias[col + 1];
            float v00 = acc[mt][nt8][0] + b0, v01 = acc[mt][nt8][1] + b1;
            float v10 = acc[mt][nt8][2] + b0, v11 = acc[mt][nt8][3] + b1;
            if (Yhi) {
                __half h00 = __float2half_rn(v00), h01 = __float2half_rn(v01);
                __half h10 = __float2half_rn(v10), h11 = __float2half_rn(v11);
                __half l00 = __float2half_rn(v00 - __half2float(h00));
                __half l01 = __float2half_rn(v01 - __half2float(h01));
                __half l10 = __float2half_rn(v10 - __half2float(h10));
                __half l11 = __float2half_rn(v11 - __half2float(h11));
                *(__half2*)(Yhi + (size_t)row * DDIM + col)       = __halves2half2(h00, h01);
                *(__half2*)(Ylo + (size_t)row * DDIM + col)       = __halves2half2(l00, l01);
                *(__half2*)(Yhi + (size_t)(row + 8) * DDIM + col) = __halves2half2(h10, h11);
                *(__half2*)(Ylo + (size_t)(row + 8) * DDIM + col) = __halves2half2(l10, l11);
            } else {
                float* y0 = Y + (size_t)row * DDIM + col;
                float* y1 = Y + (size_t)(row + 8) * DDIM + col;
                y0[0] = v00; y0[1] = v01;
                y1[0] = v10; y1[1] = v11;
            }
        }
    }
}

// ---------------------------------------------------------------------------
// Flash attention, tensor-core (f16 split). BM=128/CTA, 8 warps x 16 rows,
// BN=128, Hd=128. P via ex2.approx.f16x2; row-sum l via ones-column MMA.
// smem: Q/K/V hi+lo = 6 x 32KB = 192KB.
// ---------------------------------------------------------------------------
#define FKS 0.12751744f   // (1/sqrt(128)) * log2(e)
#define FA_SMEM (6 * 32768)

// byte offset inside a 128x128 f16 tile stored as two 64-col SW128 halves
__device__ __forceinline__ uint32_t off16(uint32_t row, uint32_t cb) {
    return ((cb >> 7) << 14) + sw128((row << 7) + (cb & 127));
}

__global__ __launch_bounds__(256)
void flash_mma_k(const __half* __restrict__ Qhi, const __half* __restrict__ Qlo,
                 const __half* __restrict__ Khi, const __half* __restrict__ Klo,
                 const __half* __restrict__ Vhi, const __half* __restrict__ Vlo,
                 float* __restrict__ O)
{
    extern __shared__ char fsm[];
    char* cQh = fsm;
    char* cQl = fsm + 32768;
    char* cKh = fsm + 65536;
    char* cKl = fsm + 98304;
    char* cVh = fsm + 131072;
    char* cVl = fsm + 163840;
    const uint32_t sQh = smem_u32(fsm);
    const uint32_t sQl = sQh + 32768;
    const uint32_t sKh = sQh + 65536;
    const uint32_t sKl = sQh + 98304;
    const uint32_t sVh = sQh + 131072;
    const uint32_t sVl = sQh + 163840;

    const int tid  = threadIdx.x;
    const int wid  = tid >> 5;
    const int lane = tid & 31;
    const int qt = blockIdx.x, h = blockIdx.y, b = blockIdx.z;
    const int wr = wid << 4;                 // warp's 16 q-rows
    const int hc = h * HDIM;
    const size_t rowbase = (size_t)b * SEQ;

    // load Q tile (hi+lo)
    for (int i = tid; i < 2048; i += 256) {
        const uint32_t row = i >> 4;
        const uint32_t cb  = (i & 15) * 16;
        const size_t g = (rowbase + qt * 128 + row) * DDIM + hc + (cb >> 1);
        const uint32_t off = off16(row, cb);
        *(uint4*)(cQh + off) = *(const uint4*)(Qhi + g);
        *(uint4*)(cQl + off) = *(const uint4*)(Qlo + g);
    }

    float o[17][4];
#pragma unroll
    for (int t = 0; t < 17; t++)
#pragma unroll
        for (int q = 0; q < 4; q++) o[t][q] = 0.f;
    float m_lo = -1e30f, m_hi = -1e30f;

    const uint32_t b_ones = (lane < 4) ? 0x3C003C00u : 0u;

    for (int jt = 0; jt < SEQ / 128; jt++) {
        __syncthreads();
        for (int i = tid; i < 2048; i += 256) {
            const uint32_t row = i >> 4;
            const uint32_t cb  = (i & 15) * 16;
            const size_t g = (rowbase + jt * 128 + row) * DDIM + hc + (cb >> 1);
            const uint32_t off = off16(row, cb);
            *(uint4*)(cKh + off) = *(const uint4*)(Khi + g);
            *(uint4*)(cKl + off) = *(const uint4*)(Klo + g);
            *(uint4*)(cVh + off) = *(const uint4*)(Vhi + g);
            *(uint4*)(cVl + off) = *(const uint4*)(Vlo + g);
        }
        __syncthreads();

        // ---- scores S = Q.K^T (split f16: 3 MMA) ----
        float s[16][4];
#pragma unroll
        for (int t = 0; t < 16; t++)
#pragma unroll
            for (int q = 0; q < 4; q++) s[t][q] = 0.f;

#pragma unroll
        for (int ks = 0; ks < 8; ks++) {
            const uint32_t kb = ks * 32;
            uint32_t ah[4], al[4];
            const uint32_t aoff = off16(wr + (lane & 15), kb + ((lane >> 4) << 4));
            ldmx4(ah, sQh + aoff);
            ldmx4(al, sQl + aoff);
#pragma unroll
            for (int ntp = 0; ntp < 8; ntp++) {
                uint32_t bh[4], bl[4];
                const uint32_t nr  = ntp * 16 + (lane & 7) + ((lane >> 4) << 3);
                const uint32_t boff = off16(nr, kb + (((lane >> 3) & 1) << 4));
                ldmx4(bh, sKh + boff);
                ldmx4(bl, sKl + boff);
#pragma unroll
                for (int hh = 0; hh < 2; hh++) {
                    float* c = s[ntp * 2 + hh];
                    mma_f16(c, ah, bh[2 * hh], bh[2 * hh + 1]);
                    mma_f16(c, ah, bl[2 * hh], bl[2 * hh + 1]);
                    mma_f16(c, al, bh[2 * hh], bh[2 * hh + 1]);
                }
            }
        }

        // ---- online softmax ----
        float mloc_lo = -1e30f, mloc_hi = -1e30f;
#pragma unroll
        for (int t = 0; t < 16; t++) {
            mloc_lo = fmaxf(mloc_lo, fmaxf(s[t][0], s[t][1]));
            mloc_hi = fmaxf(mloc_hi, fmaxf(s[t][2], s[t][3]));
        }
        mloc_lo = fmaxf(mloc_lo, __shfl_xor_sync(0xffffffffu, mloc_lo, 1));
        mloc_lo = fmaxf(mloc_lo, __shfl_xor_sync(0xffffffffu, mloc_lo, 2));
        mloc_hi = fmaxf(mloc_hi, __shfl_xor_sync(0xffffffffu, mloc_hi, 1));
        mloc_hi = fmaxf(mloc_hi, __shfl_xor_sync(0xffffffffu, mloc_hi, 2));

        const float mn_lo = fmaxf(m_lo, mloc_lo);
        const float mn_hi = fmaxf(m_hi, mloc_hi);
        const float al_lo = ex2f((m_lo - mn_lo) * FKS);
        const float al_hi = ex2f((m_hi - mn_hi) * FKS);
        m_lo = mn_lo; m_hi = mn_hi;
        const float mk_lo = mn_lo * FKS;
        const float mk_hi = mn_hi * FKS;

        uint32_t pex[16][2];
#pragma unroll
        for (int t = 0; t < 16; t++) {
            pex[t][0] = exp2x2(fmaf(s[t][0], FKS, -mk_lo), fmaf(s[t][1], FKS, -mk_lo));
            pex[t][1] = exp2x2(fmaf(s[t][2], FKS, -mk_hi), fmaf(s[t][3], FKS, -mk_hi));
        }
#pragma unroll
        for (int t = 0; t < 17; t++) {
            o[t][0] *= al_lo; o[t][1] *= al_lo;
            o[t][2] *= al_hi; o[t][3] *= al_hi;
        }

        // ---- AV: O += P.V (split V: 2 MMA) + l via ones column ----
#pragma unroll
        for (int ks = 0; ks < 8; ks++) {
            uint32_t a[4] = { pex[2 * ks][0], pex[2 * ks][1],
                              pex[2 * ks + 1][0], pex[2 * ks + 1][1] };
            const uint32_t vr = ks * 16 + (lane & 15);
#pragma unroll
            for (int dp = 0; dp < 8; dp++) {
                uint32_t vh[4], vl[4];
                const uint32_t voff = off16(vr, dp * 32 + ((lane >> 4) << 4));
                ldmx4t(vh, sVh + voff);
                ldmx4t(vl, sVl + voff);
                mma_f16(o[2 * dp],     a, vh[0], vh[1]);
                mma_f16(o[2 * dp],     a, vl[0], vl[1]);
                mma_f16(o[2 * dp + 1], a, vh[2], vh[3]);
                mma_f16(o[2 * dp + 1], a, vl[2], vl[3]);
            }
            mma_f16(o[16], a, b_ones, b_ones);
        }
    }

    // epilogue: divide by l, store fp32
    const float l_lo = __shfl_sync(0xffffffffu, o[16][0], lane & 28);
    const float l_hi = __shfl_sync(0xffffffffu, o[16][2], lane & 28);
    const float inv_lo = 1.f / l_lo;
    const float inv_hi = 1.f / l_hi;
    const size_t rg = rowbase + qt * 128 + wr + (lane >> 2);
    const int cb2 = hc + 2 * (lane & 3);
#pragma unroll
    for (int t = 0; t < 16; t++) {
        float2 v0 = make_float2(o[t][0] * inv_lo, o[t][1] * inv_lo);
        float2 v1 = make_float2(o[t][2] * inv_hi, o[t][3] * inv_hi);
        *(float2*)(O + rg * DDIM + cb2 + 8 * t)       = v0;
        *(float2*)(O + (rg + 8) * DDIM + cb2 + 8 * t) = v1;
    }
}

// ---------------------------------------------------------------------------
extern "C" void kernel_launch(void* const* d_in, const int* in_sizes, int n_in,
                              void* d_out, int out_size)
{
    (void)in_sizes; (void)n_in; (void)out_size;
    const float* query  = (const float*)d_in[0];
    const float* key_in = (const float*)d_in[1];
    const float* value  = (const float*)d_in[2];
    const float* Wq = (const float*)d_in[3];
    const float* bq = (const float*)d_in[4];
    const float* Wk = (const float*)d_in[5];
    const float* bk = (const float*)d_in[6];
    const float* Wv = (const float*)d_in[7];
    const float* bv = (const float*)d_in[8];
    const float* Wo = (const float*)d_in[9];
    const float* bo = (const float*)d_in[10];
    float* out = (float*)d_out;

    __half *pQh, *pQl, *pKh, *pKl, *pVh, *pVl;
    float* pA;
    cudaGetSymbolAddress((void**)&pQh, g_Qhi);
    cudaGetSymbolAddress((void**)&pQl, g_Qlo);
    cudaGetSymbolAddress((void**)&pKh, g_Khi);
    cudaGetSymbolAddress((void**)&pKl, g_Klo);
    cudaGetSymbolAddress((void**)&pVh, g_Vhi);
    cudaGetSymbolAddress((void**)&pVl, g_Vlo);
    cudaGetSymbolAddress((void**)&pA, g_Att);

    cudaFuncSetAttribute(gemm_mma_k,
                         cudaFuncAttributeMaxDynamicSharedMemorySize, GT_SMEM);
    cudaFuncSetAttribute(flash_mma_k,
                         cudaFuncAttributeMaxDynamicSharedMemorySize, FA_SMEM);

    dim3 gg(DDIM / 128, MROWS / 128);
    gemm_mma_k<<<gg, 512, GT_SMEM>>>(query,  Wq, bq, nullptr, pQh, pQl);
    gemm_mma_k<<<gg, 512, GT_SMEM>>>(key_in, Wk, bk, nullptr, pKh, pKl);
    gemm_mma_k<<<gg, 512, GT_SMEM>>>(value,  Wv, bv, nullptr, pVh, pVl);

    flash_mma_k<<<dim3(SEQ / 128, NHEADS, BATCH), 256, FA_SMEM>>>(
        pQh, pQl, pKh, pKl, pVh, pVl, pA);

    gemm_mma_k<<<gg, 512, GT_SMEM>>>(pA, Wo, bo, out, nullptr, nullptr);
}